// round 4
// baseline (speedup 1.0000x reference)
#include <cuda_runtime.h>
#include <cuda_bf16.h>
#include <cstdint>
#include <math.h>

constexpr int kT = 4, kB = 8, kC = 384, kN = 1024;
constexpr int kBCN  = kB * kC * kN;
constexpr int kTBCN = kT * kBCN;            // 12,582,912
constexpr float kEPS = 1e-5f;
constexpr int kWelems = kC * kC;            // 147456

// ---------------- device scratch ----------------
__device__ __nv_bfloat16 g_wqkv[9 * kWelems];   // [branch*3+split][m][k]
__device__ __nv_bfloat16 g_wp[3 * kWelems];     // [split][m][k]
__device__ __nv_bfloat16 g_sx[kTBCN];           // input spikes  [t][b][n][c]
__device__ __nv_bfloat16 g_qb[kTBCN];           // q spikes      [t][b][n][c]
__device__ float g_kvsum[kT * kB * kC];
__device__ uint32_t g_kvsb[kT * kB * kC / 2];   // kv spikes as bf16x2 pairs

// ---------------- helpers ----------------
__device__ __forceinline__ uint32_t smem_u32(const void* p) {
    uint32_t a;
    asm("{ .reg .u64 t; cvta.to.shared.u64 t, %1; cvt.u32.u64 %0, t; }" : "=r"(a) : "l"(p));
    return a;
}
__device__ __forceinline__ void cp16(uint32_t dst, const void* src) {
    asm volatile("cp.async.cg.shared.global [%0], [%1], 16;" :: "r"(dst), "l"(src));
}
__device__ __forceinline__ void ldm_x4(uint32_t* r, uint32_t addr) {
    asm volatile("ldmatrix.sync.aligned.m8n8.x4.shared.b16 {%0,%1,%2,%3}, [%4];"
                 : "=r"(r[0]), "=r"(r[1]), "=r"(r[2]), "=r"(r[3]) : "r"(addr));
}
__device__ __forceinline__ void mma16816(float* c, const uint32_t* a, uint32_t b0, uint32_t b1) {
    asm volatile("mma.sync.aligned.m16n8k16.row.col.f32.bf16.bf16.f32 "
                 "{%0,%1,%2,%3}, {%4,%5,%6,%7}, {%8,%9}, {%0,%1,%2,%3};"
                 : "+f"(c[0]), "+f"(c[1]), "+f"(c[2]), "+f"(c[3])
                 : "r"(a[0]), "r"(a[1]), "r"(a[2]), "r"(a[3]), "r"(b0), "r"(b1));
}
__device__ __forceinline__ uint32_t hmul2u(uint32_t a, uint32_t b) {
    __nv_bfloat162 r = __hmul2(*(__nv_bfloat162*)&a, *(__nv_bfloat162*)&b);
    return *(uint32_t*)&r;
}

// ---------------------------------------------------------------------------
// K0: split fp32 weights into 3 exact bf16 terms; zero kvsum.
// ---------------------------------------------------------------------------
__global__ void split_w_kernel(const float* __restrict__ qw, const float* __restrict__ kw,
                               const float* __restrict__ vw, const float* __restrict__ pw) {
    int idx = blockIdx.x * 256 + threadIdx.x;
    if (idx < kT * kB * kC) g_kvsum[idx] = 0.0f;
    if (idx >= 4 * kWelems) return;
    int mat = idx / kWelems;
    int e = idx - mat * kWelems;
    const float* src = (mat == 0) ? qw : (mat == 1) ? kw : (mat == 2) ? vw : pw;
    float w = src[e];
    __nv_bfloat16 h = __float2bfloat16(w);
    float r1 = w - __bfloat162float(h);
    __nv_bfloat16 m = __float2bfloat16(r1);
    float r2 = r1 - __bfloat162float(m);
    __nv_bfloat16 l = __float2bfloat16(r2);
    if (mat < 3) {
        g_wqkv[(mat * 3 + 0) * kWelems + e] = h;
        g_wqkv[(mat * 3 + 1) * kWelems + e] = m;
        g_wqkv[(mat * 3 + 2) * kWelems + e] = l;
    } else {
        g_wp[0 * kWelems + e] = h;
        g_wp[1 * kWelems + e] = m;
        g_wp[2 * kWelems + e] = l;
    }
}

// ---------------------------------------------------------------------------
// K1: LIF on x [t][b][c][n] -> bf16 spikes transposed to [t][b][n][c].
// ---------------------------------------------------------------------------
__global__ void lif_x_kernel(const float* __restrict__ x) {
    __shared__ __nv_bfloat16 sm[32][36];
    const int lane = threadIdx.x & 31, wid = threadIdx.x >> 5;
    const int n0 = blockIdx.x * 32, c0 = blockIdx.y * 32, b = blockIdx.z;
    float v[4] = {0.f, 0.f, 0.f, 0.f};
    for (int t = 0; t < kT; t++) {
#pragma unroll
        for (int j = 0; j < 4; j++) {
            int c = c0 + wid * 4 + j;
            float xv = x[((size_t)((t * kB + b) * kC + c)) * kN + n0 + lane];
            v[j] += (xv - v[j]) * 0.5f;
            float s = 0.f;
            if (v[j] >= 0.5f) { s = 1.f; v[j] = 0.f; }
            sm[lane][wid * 4 + j] = __float2bfloat16(s);
        }
        __syncthreads();
        int nr = wid * 4 + (lane >> 3);
        int cw = (lane & 7) * 4;
        uint2 val = *(const uint2*)&sm[nr][cw];
        *(uint2*)&g_sx[((size_t)((t * kB + b) * kN + n0 + nr)) * kC + c0 + cw] = val;
        __syncthreads();
    }
}

// ---------------------------------------------------------------------------
// FUSED QKV: per CTA tile (m:64, n:128, b). For branch k,v,q: GEMM over all
// 4 timesteps (t packed into N), then BN+LIF in registers.
//  k: record spike mask; v: AND + popcount -> g_kvsum; q: spikes -> g_qb.
// ---------------------------------------------------------------------------
constexpr int FBM = 64, FBN = 128, FBK = 64, FP = 72;
constexpr int FA_ELEMS = 3 * FBM * FP;          // 13824
constexpr int FB_ELEMS = 4 * FBN * FP;          // 36864
constexpr int FSTAGE   = FA_ELEMS + FB_ELEMS;   // 50688 elems
constexpr int FSMEM    = 2 * FSTAGE * 2;        // 202752 B

__global__ __launch_bounds__(256, 1) void fused_qkv_kernel(
    const float* __restrict__ qg, const float* __restrict__ qbe, const float* __restrict__ qm, const float* __restrict__ qva,
    const float* __restrict__ kg, const float* __restrict__ kbe, const float* __restrict__ km, const float* __restrict__ kva,
    const float* __restrict__ vg, const float* __restrict__ vbe, const float* __restrict__ vm, const float* __restrict__ vva)
{
    extern __shared__ char dynsm[];
    const uint32_t shb = smem_u32(dynsm);
    const int tid = threadIdx.x, wid = tid >> 5, lane = tid & 31;
    const int nw = wid & 3, mw = wid >> 2;           // 4 x 2 warp grid
    const int gr = lane >> 2, gc = (lane & 3) * 2;
    const int ldrow = lane & 15, ldhalf = lane >> 4;
    const int b = blockIdx.z, m0 = blockIdx.y * FBM, n0 = blockIdx.x * FBN;

    auto load_chunk = [&](const __nv_bfloat16* Ab, int k0, int st) {
        const uint32_t sb = shb + st * FSTAGE * 2;
#pragma unroll
        for (int it = 0; it < 6; it++) {
            int i = it * 256 + tid;
            int sp = i >> 9, rem = i & 511, r = rem >> 3, kq = rem & 7;
            cp16(sb + ((sp * FBM + r) * FP + kq * 8) * 2,
                 Ab + (size_t)sp * kWelems + (size_t)(m0 + r) * kC + k0 + kq * 8);
        }
#pragma unroll
        for (int it = 0; it < 16; it++) {
            int i = it * 256 + tid;
            int t = i >> 10, rem = i & 1023, r = rem >> 3, kq = rem & 7;
            cp16(sb + (FA_ELEMS + (t * FBN + r) * FP + kq * 8) * 2,
                 g_sx + ((size_t)(t * kB + b) * kN + n0 + r) * kC + k0 + kq * 8);
        }
        asm volatile("cp.async.commit_group;");
    };

    uint32_t kmask[4] = {0, 0, 0, 0};

    for (int pi = 0; pi < 3; pi++) {
        const int pbr = (pi == 0) ? 1 : ((pi == 1) ? 2 : 0);   // k, v, q
        const __nv_bfloat16* Ab = g_wqkv + (size_t)(pbr * 3) * kWelems;

        float acc[4][2][4][4];
#pragma unroll
        for (int t = 0; t < 4; t++)
#pragma unroll
            for (int mi = 0; mi < 2; mi++)
#pragma unroll
                for (int nj = 0; nj < 4; nj++)
#pragma unroll
                    for (int q = 0; q < 4; q++) acc[t][mi][nj][q] = 0.f;

        load_chunk(Ab, 0, 0);
        for (int ch = 0; ch < 6; ch++) {
            if (ch + 1 < 6) {
                load_chunk(Ab, (ch + 1) * FBK, (ch + 1) & 1);
                asm volatile("cp.async.wait_group 1;");
            } else {
                asm volatile("cp.async.wait_group 0;");
            }
            __syncthreads();
            const uint32_t sb = shb + (ch & 1) * FSTAGE * 2;
#pragma unroll
            for (int ks = 0; ks < 4; ks++) {
                uint32_t bfr[4][2][4];
#pragma unroll
                for (int t = 0; t < 4; t++)
#pragma unroll
                    for (int g = 0; g < 2; g++)
                        ldm_x4(bfr[t][g], sb + (FA_ELEMS + (t * FBN + nw * 32 + g * 16 + ldrow) * FP + ks * 16 + ldhalf * 8) * 2);
#pragma unroll
                for (int sp = 0; sp < 3; sp++) {
                    uint32_t afr[2][4];
#pragma unroll
                    for (int mi = 0; mi < 2; mi++)
                        ldm_x4(afr[mi], sb + ((sp * FBM + mw * 32 + mi * 16 + ldrow) * FP + ks * 16 + ldhalf * 8) * 2);
#pragma unroll
                    for (int t = 0; t < 4; t++)
#pragma unroll
                        for (int mi = 0; mi < 2; mi++)
#pragma unroll
                            for (int nj = 0; nj < 4; nj++)
                                mma16816(acc[t][mi][nj], afr[mi],
                                         bfr[t][nj >> 1][nj & 1], bfr[t][nj >> 1][(nj & 1) + 2]);
                }
            }
            __syncthreads();
        }

        // ---- BN + LIF epilogue (registers only, except q staging) ----
        const float *G, *Be, *Mn, *Va;
        if (pbr == 0)      { G = qg; Be = qbe; Mn = qm; Va = qva; }
        else if (pbr == 1) { G = kg; Be = kbe; Mn = km; Va = kva; }
        else               { G = vg; Be = vbe; Mn = vm; Va = vva; }

        float scv[2][2], mnv[2][2], bev[2][2];
#pragma unroll
        for (int mi = 0; mi < 2; mi++)
#pragma unroll
            for (int half = 0; half < 2; half++) {
                int cc = m0 + mw * 32 + mi * 16 + half * 8 + gr;
                scv[mi][half] = G[cc] / sqrtf(Va[cc] + kEPS);
                mnv[mi][half] = Mn[cc];
                bev[mi][half] = Be[cc];
            }

        float vst[2][4][4];
#pragma unroll
        for (int mi = 0; mi < 2; mi++)
#pragma unroll
            for (int nj = 0; nj < 4; nj++)
#pragma unroll
                for (int q = 0; q < 4; q++) vst[mi][nj][q] = 0.f;

        for (int t = 0; t < 4; t++) {
            if (pi == 0) kmask[t] = 0;
            int cnt[2][2] = {{0, 0}, {0, 0}};
#pragma unroll
            for (int mi = 0; mi < 2; mi++)
#pragma unroll
                for (int nj = 0; nj < 4; nj++)
#pragma unroll
                    for (int q = 0; q < 4; q++) {
                        int half = q >> 1;
                        float u = (acc[t][mi][nj][q] - mnv[mi][half]) * scv[mi][half] + bev[mi][half];
                        float vv = vst[mi][nj][q];
                        vv += (u - vv) * 0.5f;
                        bool s = (vv >= 0.5f);
                        if (s) vv = 0.f;
                        vst[mi][nj][q] = vv;
                        int bit = (mi * 4 + nj) * 4 + q;
                        if (pi == 0) {
                            if (s) kmask[t] |= (1u << bit);
                        } else if (pi == 1) {
                            if (s && ((kmask[t] >> bit) & 1u)) cnt[mi][half]++;
                        } else {
                            int n = nw * 32 + nj * 8 + gc + (q & 1);
                            int cl = mw * 32 + mi * 16 + half * 8 + gr;
                            *reinterpret_cast<__nv_bfloat16*>(dynsm + ((t * FBN + n) * 64 + cl) * 2) =
                                __float2bfloat16(s ? 1.f : 0.f);
                        }
                    }
            if (pi == 1) {
#pragma unroll
                for (int mi = 0; mi < 2; mi++)
#pragma unroll
                    for (int half = 0; half < 2; half++) {
                        int v_ = cnt[mi][half];
                        v_ += __shfl_xor_sync(0xffffffffu, v_, 1);
                        v_ += __shfl_xor_sync(0xffffffffu, v_, 2);
                        if ((lane & 3) == 0) {
                            int cc = m0 + mw * 32 + mi * 16 + half * 8 + gr;
                            atomicAdd(&g_kvsum[(t * kB + b) * kC + cc], (float)v_);
                        }
                    }
            }
        }
    }

    // ---- coalesced transposed store of q spikes ----
    __syncthreads();
#pragma unroll
    for (int it = 0; it < 16; it++) {
        int i = it * 256 + tid;
        int t = i >> 10, rem = i & 1023, n = rem >> 3, w = rem & 7;
        uint4 val = *reinterpret_cast<uint4*>(dynsm + ((t * FBN + n) * 64 + w * 8) * 2);
        *reinterpret_cast<uint4*>(g_qb + ((size_t)(t * kB + b) * kN + n0 + n) * kC + m0 + w * 8) = val;
    }
}

// ---------------------------------------------------------------------------
// K4: talking heads + LIF on kv; writes kv spikes as bf16.
// ---------------------------------------------------------------------------
__global__ void kv_kernel(const float* __restrict__ th_w) {
    __shared__ float th[64];
    if (threadIdx.x < 64) th[threadIdx.x] = th_w[threadIdx.x];
    __syncthreads();
    int d = threadIdx.x % 48;
    int b = threadIdx.x / 48;
    float v[8];
#pragma unroll
    for (int o = 0; o < 8; o++) v[o] = 0.0f;
#pragma unroll
    for (int t = 0; t < kT; t++) {
        float kvv[8];
#pragma unroll
        for (int h = 0; h < 8; h++)
            kvv[h] = g_kvsum[(t * kB + b) * kC + h * 48 + d];
#pragma unroll
        for (int o = 0; o < 8; o++) {
            float a = 0.0f;
#pragma unroll
            for (int h = 0; h < 8; h++) a += th[o * 8 + h] * kvv[h];
            v[o] += (a - v[o]) * 0.5f;
            float s = 0.f;
            if (v[o] >= 0.5f) { s = 1.f; v[o] = 0.f; }
            ((__nv_bfloat16*)g_kvsb)[(t * kB + b) * kC + o * 48 + d] = __float2bfloat16(s);
        }
    }
}

// ---------------------------------------------------------------------------
// PROJ GEMM (HMMA): B = q spikes * kvs (kvs folded in post-ldmatrix, exact).
// Epilogue: +bias, BN, +identity.
// ---------------------------------------------------------------------------
constexpr int BM = 128, BN = 128, BK = 32;
constexpr int PITCH = 40;
constexpr int A_ELEMS = 3 * BM * PITCH;
constexpr int B_ELEMS = BN * PITCH;
constexpr int STAGE_ELEMS = A_ELEMS + B_ELEMS;
constexpr int SMEM_BYTES = 2 * STAGE_ELEMS * 2;

__global__ __launch_bounds__(256, 2) void gemm_proj_kernel(
    const float* __restrict__ pg, const float* __restrict__ pbe,
    const float* __restrict__ pm, const float* __restrict__ pva,
    const float* __restrict__ bias, const float* __restrict__ xres, float* __restrict__ outp)
{
    extern __shared__ __nv_bfloat16 sh[];
    const uint32_t shb = smem_u32(sh);

    const int tid = threadIdx.x, wid = tid >> 5, lane = tid & 31;
    const int bz = blockIdx.z, t = bz >> 3, b = bz & 7;
    const int m0 = blockIdx.y * BM, n0 = blockIdx.x * BN;

    const __nv_bfloat16* Bimg = g_qb + (size_t)(t * kB + b) * kN * kC;
    const uint32_t* kvsb = g_kvsb + (t * kB + b) * (kC / 2);

    const int mw = wid >> 1, nw = wid & 1;

    float acc[2][8][4];
#pragma unroll
    for (int i = 0; i < 2; i++)
#pragma unroll
        for (int j = 0; j < 8; j++)
#pragma unroll
            for (int q = 0; q < 4; q++) acc[i][j][q] = 0.f;

    auto load_chunk = [&](int ck, int st) {
        const uint32_t sb = shb + st * STAGE_ELEMS * 2;
        const int k0 = ck * BK;
#pragma unroll
        for (int it = 0; it < 6; it++) {
            int i = it * 256 + tid;
            int sp = i >> 9, rem = i & 511, r = rem >> 2, kq = rem & 3;
            cp16(sb + (sp * BM * PITCH + r * PITCH + kq * 8) * 2,
                 g_wp + (size_t)sp * kWelems + (size_t)(m0 + r) * kC + k0 + kq * 8);
        }
#pragma unroll
        for (int it = 0; it < 2; it++) {
            int i = it * 256 + tid;
            int r = i >> 2, kq = i & 3;
            cp16(sb + (A_ELEMS + r * PITCH + kq * 8) * 2,
                 Bimg + (size_t)(n0 + r) * kC + k0 + kq * 8);
        }
        asm volatile("cp.async.commit_group;");
    };

    load_chunk(0, 0);
    const int ldrow = lane & 15, ldhalf = lane >> 4;

    for (int cch = 0; cch < kC / BK; cch++) {
        if (cch + 1 < kC / BK) {
            load_chunk(cch + 1, (cch + 1) & 1);
            asm volatile("cp.async.wait_group 1;");
        } else {
            asm volatile("cp.async.wait_group 0;");
        }
        __syncthreads();
        const uint32_t sb = shb + (cch & 1) * STAGE_ELEMS * 2;
#pragma unroll
        for (int ks = 0; ks < 2; ks++) {
            const int k0 = ks * 16;
            uint32_t bfr[16];
#pragma unroll
            for (int g = 0; g < 4; g++) {
                uint32_t addr = sb + (A_ELEMS + (nw * 64 + g * 16 + ldrow) * PITCH + k0 + ldhalf * 8) * 2;
                ldm_x4(&bfr[g * 4], addr);
            }
            // fold kvs (per-k scale, binary -> exact)
            uint32_t p0 = kvsb[cch * 16 + ks * 8 + (lane & 3)];
            uint32_t p1 = kvsb[cch * 16 + ks * 8 + 4 + (lane & 3)];
#pragma unroll
            for (int g = 0; g < 4; g++) {
                bfr[g * 4 + 0] = hmul2u(bfr[g * 4 + 0], p0);
                bfr[g * 4 + 1] = hmul2u(bfr[g * 4 + 1], p0);
                bfr[g * 4 + 2] = hmul2u(bfr[g * 4 + 2], p1);
                bfr[g * 4 + 3] = hmul2u(bfr[g * 4 + 3], p1);
            }
#pragma unroll
            for (int sp = 0; sp < 3; sp++) {
                uint32_t afr[2][4];
#pragma unroll
                for (int mi = 0; mi < 2; mi++) {
                    uint32_t addr = sb + (sp * BM * PITCH + (mw * 32 + mi * 16 + ldrow) * PITCH + k0 + ldhalf * 8) * 2;
                    ldm_x4(afr[mi], addr);
                }
#pragma unroll
                for (int mi = 0; mi < 2; mi++)
#pragma unroll
                    for (int nj = 0; nj < 8; nj++) {
                        int g = nj >> 1, w = nj & 1;
                        mma16816(acc[mi][nj], afr[mi], bfr[g * 4 + w], bfr[g * 4 + w + 2]);
                    }
            }
        }
        __syncthreads();
    }

    const int gr = lane >> 2, gc = (lane & 3) * 2;
    const size_t imgoff = ((size_t)(t * kB + b) * kC) * kN;

#pragma unroll
    for (int mi = 0; mi < 2; mi++) {
#pragma unroll
        for (int half = 0; half < 2; half++) {
            const int c = m0 + mw * 32 + mi * 16 + gr + half * 8;
            const float sc = pg[c] / sqrtf(pva[c] + kEPS);
            const float mn = pm[c], be = pbe[c];
            const float bi = bias[c];
            size_t rowoff = imgoff + (size_t)c * kN;
            float* dst = outp + rowoff;
#pragma unroll
            for (int nj = 0; nj < 8; nj++) {
                const int n = n0 + nw * 64 + nj * 8 + gc;
                float v0 = acc[mi][nj][half * 2 + 0];
                float v1 = acc[mi][nj][half * 2 + 1];
                float2 xv = *(const float2*)(xres + rowoff + n);
                float2 o;
                o.x = ((v0 + bi) - mn) * sc + be + xv.x;
                o.y = ((v1 + bi) - mn) * sc + be + xv.y;
                *(float2*)(dst + n) = o;
            }
        }
    }
}

// ---------------------------------------------------------------------------
extern "C" void kernel_launch(void* const* d_in, const int* in_sizes, int n_in,
                              void* d_out, int out_size)
{
    const float* x   = (const float*)d_in[0];
    const float* qw  = (const float*)d_in[1];
    const float* kw  = (const float*)d_in[2];
    const float* vw  = (const float*)d_in[3];
    const float* thw = (const float*)d_in[4];
    const float* pw  = (const float*)d_in[5];
    const float* pb  = (const float*)d_in[6];
    const float* qg  = (const float*)d_in[7];
    const float* qbe = (const float*)d_in[8];
    const float* qm  = (const float*)d_in[9];
    const float* qva = (const float*)d_in[10];
    const float* kg  = (const float*)d_in[11];
    const float* kbe = (const float*)d_in[12];
    const float* km  = (const float*)d_in[13];
    const float* kva = (const float*)d_in[14];
    const float* vg  = (const float*)d_in[15];
    const float* vbe = (const float*)d_in[16];
    const float* vm  = (const float*)d_in[17];
    const float* vva = (const float*)d_in[18];
    const float* pg  = (const float*)d_in[19];
    const float* pbe = (const float*)d_in[20];
    const float* pm  = (const float*)d_in[21];
    const float* pva = (const float*)d_in[22];
    float* out = (float*)d_out;

    cudaFuncSetAttribute(fused_qkv_kernel, cudaFuncAttributeMaxDynamicSharedMemorySize, FSMEM);
    cudaFuncSetAttribute(gemm_proj_kernel, cudaFuncAttributeMaxDynamicSharedMemorySize, SMEM_BYTES);

    split_w_kernel<<<(4 * kWelems + 255) / 256, 256>>>(qw, kw, vw, pw);

    lif_x_kernel<<<dim3(kN / 32, kC / 32, kB), 256>>>(x);

    fused_qkv_kernel<<<dim3(kN / FBN, kC / FBM, kB), 256, FSMEM>>>(
        qg, qbe, qm, qva, kg, kbe, km, kva, vg, vbe, vm, vva);

    kv_kernel<<<1, 384>>>(thw);

    gemm_proj_kernel<<<dim3(kN / BN, kC / BM, kT * kB), 256, SMEM_BYTES>>>(
        pg, pbe, pm, pva, pb, x, out);
}

// round 5
// speedup vs baseline: 4.1674x; 4.1674x over previous
#include <cuda_runtime.h>
#include <cuda_fp16.h>
#include <cstdint>
#include <math.h>

constexpr int kT = 4, kB = 8, kC = 384, kN = 1024;
constexpr int kBCN  = kB * kC * kN;
constexpr int kTBCN = kT * kBCN;            // 12,582,912
constexpr float kEPS = 1e-5f;
constexpr int kWelems = kC * kC;            // 147456
constexpr float kLoScale = 1.0f / 4096.0f;

// ---------------- device scratch ----------------
__device__ __half g_wqkv[6 * kWelems];      // [branch*2+split][m][k]  (hi, lo*4096)
__device__ __half g_wp[2 * kWelems];        // [split][m][k]
__device__ __half g_sx[kTBCN];              // input spikes  [t][b][n][c]
__device__ __half g_qb[kTBCN];              // q spikes      [t][b][n][c]
__device__ float g_u[3ull * kTBCN];         // q/k/v pre-activations [p][t][b][c][n]
__device__ float g_kvsum[kT * kB * kC];
__device__ __half g_kvsh[kT * kB * kC];     // kv spikes (fp16)

// ---------------- helpers ----------------
__device__ __forceinline__ uint32_t smem_u32(const void* p) {
    uint32_t a;
    asm("{ .reg .u64 t; cvta.to.shared.u64 t, %1; cvt.u32.u64 %0, t; }" : "=r"(a) : "l"(p));
    return a;
}
__device__ __forceinline__ void cp16(uint32_t dst, const void* src) {
    asm volatile("cp.async.cg.shared.global [%0], [%1], 16;" :: "r"(dst), "l"(src));
}
__device__ __forceinline__ void ldm_x4(uint32_t* r, uint32_t addr) {
    asm volatile("ldmatrix.sync.aligned.m8n8.x4.shared.b16 {%0,%1,%2,%3}, [%4];"
                 : "=r"(r[0]), "=r"(r[1]), "=r"(r[2]), "=r"(r[3]) : "r"(addr));
}
__device__ __forceinline__ void mma16816(float* c, const uint32_t* a, uint32_t b0, uint32_t b1) {
    asm volatile("mma.sync.aligned.m16n8k16.row.col.f32.f16.f16.f32 "
                 "{%0,%1,%2,%3}, {%4,%5,%6,%7}, {%8,%9}, {%0,%1,%2,%3};"
                 : "+f"(c[0]), "+f"(c[1]), "+f"(c[2]), "+f"(c[3])
                 : "r"(a[0]), "r"(a[1]), "r"(a[2]), "r"(a[3]), "r"(b0), "r"(b1));
}
__device__ __forceinline__ uint32_t hmul2u(uint32_t a, uint32_t b) {
    __half2 r = __hmul2(*(__half2*)&a, *(__half2*)&b);
    return *(uint32_t*)&r;
}

// GEMM tiling: 128(M) x 64(N) x 32(K), 8 warps (4m x 2n), dual accumulators.
constexpr int BM = 128, BN = 64, BK = 32;
constexpr int PITCH = 40;                        // half elems per smem row (80B)
constexpr int A_ELEMS = 2 * BM * PITCH;          // 10240 (2 splits)
constexpr int B_ELEMS = BN * PITCH;              // 2560
constexpr int STAGE_ELEMS = A_ELEMS + B_ELEMS;   // 12800
constexpr int SMEM_BYTES = 2 * STAGE_ELEMS * 2;  // 51200

// ---------------------------------------------------------------------------
// K0: split fp32 weights into (hi, lo*4096) fp16 pair; zero kvsum.
// ---------------------------------------------------------------------------
__global__ void split_w_kernel(const float* __restrict__ qw, const float* __restrict__ kw,
                               const float* __restrict__ vw, const float* __restrict__ pw) {
    int idx = blockIdx.x * 256 + threadIdx.x;
    if (idx < kT * kB * kC) g_kvsum[idx] = 0.0f;
    if (idx >= 4 * kWelems) return;
    int mat = idx / kWelems;
    int e = idx - mat * kWelems;
    const float* src = (mat == 0) ? qw : (mat == 1) ? kw : (mat == 2) ? vw : pw;
    float w = src[e];
    __half h = __float2half_rn(w);
    __half l = __float2half_rn((w - __half2float(h)) * 4096.0f);
    if (mat < 3) {
        g_wqkv[(mat * 2 + 0) * kWelems + e] = h;
        g_wqkv[(mat * 2 + 1) * kWelems + e] = l;
    } else {
        g_wp[0 * kWelems + e] = h;
        g_wp[1 * kWelems + e] = l;
    }
}

// ---------------------------------------------------------------------------
// K1: LIF on x [t][b][c][n] -> fp16 spikes transposed to [t][b][n][c].
// ---------------------------------------------------------------------------
__global__ void lif_x_kernel(const float* __restrict__ x) {
    __shared__ __half sm[32][36];
    const int lane = threadIdx.x & 31, wid = threadIdx.x >> 5;
    const int n0 = blockIdx.x * 32, c0 = blockIdx.y * 32, b = blockIdx.z;
    float v[4] = {0.f, 0.f, 0.f, 0.f};
    for (int t = 0; t < kT; t++) {
#pragma unroll
        for (int j = 0; j < 4; j++) {
            int c = c0 + wid * 4 + j;
            float xv = x[((size_t)((t * kB + b) * kC + c)) * kN + n0 + lane];
            v[j] += (xv - v[j]) * 0.5f;
            float s = 0.f;
            if (v[j] >= 0.5f) { s = 1.f; v[j] = 0.f; }
            sm[lane][wid * 4 + j] = __float2half(s);
        }
        __syncthreads();
        int nr = wid * 4 + (lane >> 3);
        int cw = (lane & 7) * 4;
        uint2 val = *(const uint2*)&sm[nr][cw];
        *(uint2*)&g_sx[((size_t)((t * kB + b) * kN + n0 + nr)) * kC + c0 + cw] = val;
        __syncthreads();
    }
}

// ---------------------------------------------------------------------------
// GEMM via mma.sync fp16, dual-split accumulation.
// MODE 0: U = BN(W_p @ S^T) -> g_u.  MODE 1: out = BN(PW @ (Q*kvs)^T + bias) + x.
// ---------------------------------------------------------------------------
template <int MODE>
__global__ __launch_bounds__(256, 2) void gemm_kernel(
    const float* __restrict__ qg, const float* __restrict__ qbe, const float* __restrict__ qm, const float* __restrict__ qva,
    const float* __restrict__ kg, const float* __restrict__ kbe, const float* __restrict__ km, const float* __restrict__ kva,
    const float* __restrict__ vg, const float* __restrict__ vbe, const float* __restrict__ vm, const float* __restrict__ vva,
    const float* __restrict__ bias, const float* __restrict__ xres, float* __restrict__ outp)
{
    extern __shared__ __half sh[];
    const uint32_t shb = smem_u32(sh);

    const int tid = threadIdx.x, wid = tid >> 5, lane = tid & 31;
    const int bz = blockIdx.z, t = bz >> 3, b = bz & 7;
    int p, mtile;
    if (MODE == 0) { int yy = blockIdx.y; p = (yy >= 6) ? 2 : ((yy >= 3) ? 1 : 0); mtile = yy - p * 3; }
    else           { p = 0; mtile = blockIdx.y; }
    const int m0 = mtile * BM, n0 = blockIdx.x * BN;

    const __half* Abase = (MODE == 0) ? (g_wqkv + (size_t)(p * 2) * kWelems) : g_wp;
    const __half* Bimg  = ((MODE == 0) ? g_sx : g_qb) + (size_t)(t * kB + b) * kN * kC;
    const uint32_t* kvsp = (const uint32_t*)(g_kvsh + (t * kB + b) * kC);

    const int mw = wid >> 1, nw = wid & 1;      // 4m x 2n warps; warp tile 32x32

    float acch[2][4][4], accl[2][4][4];
#pragma unroll
    for (int i = 0; i < 2; i++)
#pragma unroll
        for (int j = 0; j < 4; j++)
#pragma unroll
            for (int q = 0; q < 4; q++) { acch[i][j][q] = 0.f; accl[i][j][q] = 0.f; }

    auto load_chunk = [&](int ck, int st) {
        const uint32_t sb = shb + st * STAGE_ELEMS * 2;
        const int k0 = ck * BK;
        // A: 2 splits x 128 rows x 4 x 16B = 1024 cp16
#pragma unroll
        for (int it = 0; it < 4; it++) {
            int i = it * 256 + tid;
            int sp = i >> 9, rem = i & 511, r = rem >> 2, kq = rem & 3;
            cp16(sb + ((sp * BM + r) * PITCH + kq * 8) * 2,
                 Abase + (size_t)sp * kWelems + (size_t)(m0 + r) * kC + k0 + kq * 8);
        }
        // B: 64 rows x 4 x 16B = 256 cp16
        {
            int r = tid >> 2, kq = tid & 3;
            cp16(sb + (A_ELEMS + r * PITCH + kq * 8) * 2,
                 Bimg + (size_t)(n0 + r) * kC + k0 + kq * 8);
        }
        asm volatile("cp.async.commit_group;");
    };

    load_chunk(0, 0);
    const int ldrow = lane & 15, ldhalf = lane >> 4;

    for (int cch = 0; cch < kC / BK; cch++) {
        if (cch + 1 < kC / BK) {
            load_chunk(cch + 1, (cch + 1) & 1);
            asm volatile("cp.async.wait_group 1;");
        } else {
            asm volatile("cp.async.wait_group 0;");
        }
        __syncthreads();
        const uint32_t sb = shb + (cch & 1) * STAGE_ELEMS * 2;
#pragma unroll
        for (int ks = 0; ks < 2; ks++) {
            const int k0 = ks * 16;
            uint32_t bfr[2][4];
#pragma unroll
            for (int g = 0; g < 2; g++)
                ldm_x4(bfr[g], sb + (A_ELEMS + (nw * 32 + g * 16 + ldrow) * PITCH + k0 + ldhalf * 8) * 2);
            if (MODE == 1) {
                // fold kvs (per-k scale; binary x binary -> exact)
                uint32_t p0 = kvsp[cch * 16 + ks * 8 + (lane & 3)];
                uint32_t p1 = kvsp[cch * 16 + ks * 8 + 4 + (lane & 3)];
#pragma unroll
                for (int g = 0; g < 2; g++) {
                    bfr[g][0] = hmul2u(bfr[g][0], p0);
                    bfr[g][1] = hmul2u(bfr[g][1], p0);
                    bfr[g][2] = hmul2u(bfr[g][2], p1);
                    bfr[g][3] = hmul2u(bfr[g][3], p1);
                }
            }
#pragma unroll
            for (int sp = 0; sp < 2; sp++) {
                uint32_t afr[2][4];
#pragma unroll
                for (int mi = 0; mi < 2; mi++)
                    ldm_x4(afr[mi], sb + ((sp * BM + mw * 32 + mi * 16 + ldrow) * PITCH + k0 + ldhalf * 8) * 2);
#pragma unroll
                for (int mi = 0; mi < 2; mi++)
#pragma unroll
                    for (int nj = 0; nj < 4; nj++) {
                        int g = nj >> 1, w = nj & 1;
                        float* acc = (sp == 0) ? acch[mi][nj] : accl[mi][nj];
                        mma16816(acc, afr[mi], bfr[g][w], bfr[g][w + 2]);
                    }
            }
        }
        __syncthreads();
    }

    // ---- epilogue ----
    const float *G, *Be, *Mn, *Va;
    if (MODE == 0) {
        if (p == 0)      { G = qg; Be = qbe; Mn = qm; Va = qva; }
        else if (p == 1) { G = kg; Be = kbe; Mn = km; Va = kva; }
        else             { G = vg; Be = vbe; Mn = vm; Va = vva; }
    } else             { G = qg; Be = qbe; Mn = qm; Va = qva; }

    const int gr = lane >> 2, gc = (lane & 3) * 2;
    const size_t imgoff = ((size_t)(t * kB + b) * kC) * kN;

#pragma unroll
    for (int mi = 0; mi < 2; mi++) {
#pragma unroll
        for (int half = 0; half < 2; half++) {
            const int c = m0 + mw * 32 + mi * 16 + gr + half * 8;
            const float sc = G[c] / sqrtf(Va[c] + kEPS);
            const float mn = Mn[c], be = Be[c];
            const float bi = (MODE == 1) ? bias[c] : 0.f;
            size_t rowoff;
            if (MODE == 0) rowoff = (size_t)p * kTBCN + imgoff + (size_t)c * kN;
            else           rowoff = imgoff + (size_t)c * kN;
            float* dst = ((MODE == 0) ? g_u : outp) + rowoff;
#pragma unroll
            for (int nj = 0; nj < 4; nj++) {
                const int n = n0 + nw * 32 + nj * 8 + gc;
                float v0 = acch[mi][nj][half * 2 + 0] + accl[mi][nj][half * 2 + 0] * kLoScale;
                float v1 = acch[mi][nj][half * 2 + 1] + accl[mi][nj][half * 2 + 1] * kLoScale;
                float2 o;
                if (MODE == 0) {
                    o.x = (v0 - mn) * sc + be;
                    o.y = (v1 - mn) * sc + be;
                } else {
                    float2 xv = *(const float2*)(xres + rowoff + n);
                    o.x = ((v0 + bi) - mn) * sc + be + xv.x;
                    o.y = ((v1 + bi) - mn) * sc + be + xv.y;
                }
                *(float2*)(dst + n) = o;
            }
        }
    }
}

// ---------------------------------------------------------------------------
// K3: LIF on q/k/v pre-activations. q spikes -> g_qb (transposed fp16);
// (k AND v) popcount over n -> g_kvsum.
// ---------------------------------------------------------------------------
__global__ void lif_qkv_kernel() {
    __shared__ __half sm[32][36];
    const int lane = threadIdx.x & 31, wid = threadIdx.x >> 5;
    const int n0 = blockIdx.x * 32, c0 = blockIdx.y * 32, b = blockIdx.z;
    float vq[4] = {0,0,0,0}, vk[4] = {0,0,0,0}, vv[4] = {0,0,0,0};
    for (int t = 0; t < kT; t++) {
#pragma unroll
        for (int j = 0; j < 4; j++) {
            int c = c0 + wid * 4 + j;
            size_t off = ((size_t)((t * kB + b) * kC + c)) * kN + n0 + lane;
            float uq = g_u[off];
            float uk = g_u[off + (size_t)kTBCN];
            float uv = g_u[off + 2ull * kTBCN];

            vq[j] += (uq - vq[j]) * 0.5f;
            float sq = 0.f; if (vq[j] >= 0.5f) { sq = 1.f; vq[j] = 0.f; }
            vk[j] += (uk - vk[j]) * 0.5f;
            bool sk = false; if (vk[j] >= 0.5f) { sk = true; vk[j] = 0.f; }
            vv[j] += (uv - vv[j]) * 0.5f;
            bool sv = false; if (vv[j] >= 0.5f) { sv = true; vv[j] = 0.f; }

            sm[lane][wid * 4 + j] = __float2half(sq);
            unsigned msk = __ballot_sync(0xffffffffu, sk && sv);
            if (lane == 0)
                atomicAdd(&g_kvsum[(t * kB + b) * kC + c], (float)__popc(msk));
        }
        __syncthreads();
        int nr = wid * 4 + (lane >> 3);
        int cw = (lane & 7) * 4;
        uint2 val = *(const uint2*)&sm[nr][cw];
        *(uint2*)&g_qb[((size_t)((t * kB + b) * kN + n0 + nr)) * kC + c0 + cw] = val;
        __syncthreads();
    }
}

// ---------------------------------------------------------------------------
// K4: talking heads + LIF on kv; kv spikes -> fp16.
// ---------------------------------------------------------------------------
__global__ void kv_kernel(const float* __restrict__ th_w) {
    __shared__ float th[64];
    if (threadIdx.x < 64) th[threadIdx.x] = th_w[threadIdx.x];
    __syncthreads();
    int d = threadIdx.x % 48;
    int b = threadIdx.x / 48;
    float v[8];
#pragma unroll
    for (int o = 0; o < 8; o++) v[o] = 0.0f;
#pragma unroll
    for (int t = 0; t < kT; t++) {
        float kvv[8];
#pragma unroll
        for (int h = 0; h < 8; h++)
            kvv[h] = g_kvsum[(t * kB + b) * kC + h * 48 + d];
#pragma unroll
        for (int o = 0; o < 8; o++) {
            float a = 0.0f;
#pragma unroll
            for (int h = 0; h < 8; h++) a += th[o * 8 + h] * kvv[h];
            v[o] += (a - v[o]) * 0.5f;
            float s = 0.f;
            if (v[o] >= 0.5f) { s = 1.f; v[o] = 0.f; }
            g_kvsh[(t * kB + b) * kC + o * 48 + d] = __float2half(s);
        }
    }
}

// ---------------------------------------------------------------------------
extern "C" void kernel_launch(void* const* d_in, const int* in_sizes, int n_in,
                              void* d_out, int out_size)
{
    const float* x   = (const float*)d_in[0];
    const float* qw  = (const float*)d_in[1];
    const float* kw  = (const float*)d_in[2];
    const float* vw  = (const float*)d_in[3];
    const float* thw = (const float*)d_in[4];
    const float* pw  = (const float*)d_in[5];
    const float* pb  = (const float*)d_in[6];
    const float* qg  = (const float*)d_in[7];
    const float* qbe = (const float*)d_in[8];
    const float* qm  = (const float*)d_in[9];
    const float* qva = (const float*)d_in[10];
    const float* kg  = (const float*)d_in[11];
    const float* kbe = (const float*)d_in[12];
    const float* km  = (const float*)d_in[13];
    const float* kva = (const float*)d_in[14];
    const float* vg  = (const float*)d_in[15];
    const float* vbe = (const float*)d_in[16];
    const float* vm  = (const float*)d_in[17];
    const float* vva = (const float*)d_in[18];
    const float* pg  = (const float*)d_in[19];
    const float* pbe = (const float*)d_in[20];
    const float* pm  = (const float*)d_in[21];
    const float* pva = (const float*)d_in[22];
    float* out = (float*)d_out;

    cudaFuncSetAttribute(gemm_kernel<0>, cudaFuncAttributeMaxDynamicSharedMemorySize, SMEM_BYTES);
    cudaFuncSetAttribute(gemm_kernel<1>, cudaFuncAttributeMaxDynamicSharedMemorySize, SMEM_BYTES);

    split_w_kernel<<<(4 * kWelems + 255) / 256, 256>>>(qw, kw, vw, pw);

    lif_x_kernel<<<dim3(kN / 32, kC / 32, kB), 256>>>(x);

    gemm_kernel<0><<<dim3(kN / BN, 9, kT * kB), 256, SMEM_BYTES>>>(
        qg, qbe, qm, qva, kg, kbe, km, kva, vg, vbe, vm, vva,
        nullptr, nullptr, nullptr);

    lif_qkv_kernel<<<dim3(kN / 32, kC / 32, kB), 256>>>();

    kv_kernel<<<1, 384>>>(thw);

    gemm_kernel<1><<<dim3(kN / BN, kC / BM, kT * kB), 256, SMEM_BYTES>>>(
        pg, pbe, pm, pva, pg, pbe, pm, pva, pg, pbe, pm, pva,
        pb, x, out);
}